// round 2
// baseline (speedup 1.0000x reference)
#include <cuda_runtime.h>

#define NPTS 40000
#define KN 16
#define CH 128
#define CS 16          // C / S
#define EPSBN 1e-5f

// ---------------- scratch (no allocation allowed -> __device__ globals) -------------
__device__ float g_q[NPTS * CH];
__device__ float g_k[NPTS * CH];
__device__ float g_v[NPTS * CH];
__device__ float g_W1T[CS * CH];   // folded (Ww1 * s1)^T, row j contiguous over c
__device__ float g_sw[CH];         // bn_w scale
__device__ float g_shw[CH];        // bn_w shift
__device__ float g_b1f[CS];        // folded bw1 through bn1
__device__ float g_Wp1f[9];        // Wp1 with bn_p scale folded into columns
__device__ float g_bp1f[3];

// packed fp32x2 FMA (FFMA2) — 2 FLOP-lanes per instruction on sm_103a
__device__ __forceinline__ void ffma2(unsigned long long& d,
                                      unsigned long long a,
                                      unsigned long long b) {
    asm("fma.rn.f32x2 %0, %1, %2, %0;" : "+l"(d) : "l"(a), "l"(b));
}

__device__ __forceinline__ unsigned long long dup2(float f) {
    unsigned int u = __float_as_uint(f);
    return ((unsigned long long)u << 32) | (unsigned long long)u;
}

__device__ __forceinline__ float lo32(unsigned long long v) {
    return __uint_as_float((unsigned int)v);
}
__device__ __forceinline__ float hi32(unsigned long long v) {
    return __uint_as_float((unsigned int)(v >> 32));
}

// ---------------- kernel 0: fold BN params into weights -----------------------------
__global__ void prep_kernel(const float* __restrict__ w_gamma, const float* __restrict__ w_beta,
                            const float* __restrict__ w_mean, const float* __restrict__ w_var,
                            const float* __restrict__ Ww1, const float* __restrict__ bw1,
                            const float* __restrict__ w1_gamma, const float* __restrict__ w1_beta,
                            const float* __restrict__ w1_mean, const float* __restrict__ w1_var,
                            const float* __restrict__ Wp1, const float* __restrict__ bp1,
                            const float* __restrict__ p_gamma, const float* __restrict__ p_beta,
                            const float* __restrict__ p_mean, const float* __restrict__ p_var) {
    int t = threadIdx.x;
    if (t < CH) {
        float s = w_gamma[t] * rsqrtf(w_var[t] + EPSBN);
        g_sw[t] = s;
        g_shw[t] = w_beta[t] - w_mean[t] * s;
    }
    for (int idx = t; idx < CS * CH; idx += blockDim.x) {
        int j = idx / CH, c = idx % CH;
        float s1 = w1_gamma[j] * rsqrtf(w1_var[j] + EPSBN);
        g_W1T[idx] = Ww1[c * CS + j] * s1;
    }
    if (t < CS) {
        float s1 = w1_gamma[t] * rsqrtf(w1_var[t] + EPSBN);
        g_b1f[t] = (bw1[t] - w1_mean[t]) * s1 + w1_beta[t];
    }
    if (t < 9) {
        int o = t % 3;
        float sp = p_gamma[o] * rsqrtf(p_var[o] + EPSBN);
        g_Wp1f[t] = Wp1[t] * sp;
    }
    if (t < 3) {
        float sp = p_gamma[t] * rsqrtf(p_var[t] + EPSBN);
        g_bp1f[t] = (bp1[t] - p_mean[t]) * sp + p_beta[t];
    }
}

// ---------------- kernel 1: fused q/k/v GEMM (FFMA2 register-tiled) -----------------
// C_out[40000,128] = x[40000,128] @ W[128,128] + b, blockIdx.y selects {q,k,v}
// BM=64, BN=128, BK=16; 256 threads; thread tile 8 rows x 4 cols (2 f32x2 pairs)
__global__ __launch_bounds__(256, 2) void qkv_gemm(
    const float* __restrict__ x,
    const float* __restrict__ Wq, const float* __restrict__ bq,
    const float* __restrict__ Wk, const float* __restrict__ bk,
    const float* __restrict__ Wv, const float* __restrict__ bv) {
    const float* W;
    const float* bias;
    float* out;
    if (blockIdx.y == 0)      { W = Wq; bias = bq; out = g_q; }
    else if (blockIdx.y == 1) { W = Wk; bias = bk; out = g_k; }
    else                      { W = Wv; bias = bv; out = g_v; }

    __shared__ __align__(16) unsigned long long A2s[16][64];  // A duplicated as f32x2
    __shared__ __align__(16) float Bs[16][128];

    const int tid = threadIdx.x;
    const int tm = tid >> 5;   // warp id 0..7 -> rows tm*8..tm*8+7
    const int tn = tid & 31;   // 0..31      -> cols tn*4..tn*4+3
    const int row0 = blockIdx.x * 64;

    unsigned long long acc[8][2];
#pragma unroll
    for (int r = 0; r < 8; r++) { acc[r][0] = 0ULL; acc[r][1] = 0ULL; }

    for (int kt = 0; kt < 8; kt++) {
        const int k0 = kt * 16;
        // load A tile 64x16 (one float4 per thread), store duplicated+transposed
        {
            int ar = tid >> 2;
            int ac = (tid & 3) * 4;
            float4 av = *(const float4*)&x[(row0 + ar) * CH + k0 + ac];
            A2s[ac + 0][ar] = dup2(av.x);
            A2s[ac + 1][ar] = dup2(av.y);
            A2s[ac + 2][ar] = dup2(av.z);
            A2s[ac + 3][ar] = dup2(av.w);
        }
        // load B tile 16x128 (two float4 per thread)
#pragma unroll
        for (int i = 0; i < 2; i++) {
            int f4 = tid * 2 + i;
            int bkr = f4 >> 5;
            int bc = (f4 & 31) * 4;
            *(float4*)&Bs[bkr][bc] = *(const float4*)&W[(k0 + bkr) * CH + bc];
        }
        __syncthreads();
#pragma unroll
        for (int kk = 0; kk < 16; kk++) {
            unsigned long long b0 = *(const unsigned long long*)&Bs[kk][tn * 4];
            unsigned long long b1 = *(const unsigned long long*)&Bs[kk][tn * 4 + 2];
#pragma unroll
            for (int r = 0; r < 8; r++) {
                unsigned long long a = A2s[kk][tm * 8 + r];
                ffma2(acc[r][0], a, b0);
                ffma2(acc[r][1], a, b1);
            }
        }
        __syncthreads();
    }

    const float bb0 = bias[tn * 4], bb1 = bias[tn * 4 + 1];
    const float bb2 = bias[tn * 4 + 2], bb3 = bias[tn * 4 + 3];
#pragma unroll
    for (int r = 0; r < 8; r++) {
        float4 v;
        v.x = lo32(acc[r][0]) + bb0;
        v.y = hi32(acc[r][0]) + bb1;
        v.z = lo32(acc[r][1]) + bb2;
        v.w = hi32(acc[r][1]) + bb3;
        *(float4*)&out[(row0 + tm * 8 + r) * CH + tn * 4] = v;
    }
}

// ---------------- kernel 2: fused attention per point -------------------------------
__global__ __launch_bounds__(256) void pt_main(
    const float* __restrict__ xyz, const float* __restrict__ feats,
    const int* __restrict__ nei,
    const float* __restrict__ Wp2, const float* __restrict__ bp2,
    const float* __restrict__ Ww2, const float* __restrict__ bw2,
    float* __restrict__ out) {
    __shared__ __align__(16) float wv_s[KN][CH];    // relu(bn_w(kf - q + p))
    __shared__ __align__(16) float vfp_s[KN][CH];   // vf + p
    __shared__ float t_s[KN][4];                    // relu'd positional 3-vector
    __shared__ int nb_s[KN];
    __shared__ float h2_s[KN][CS];
    __shared__ float lg_s[KN][CS];
    __shared__ float wgt_s[KN][CS];

    const int n = blockIdx.x;
    const int tid = threadIdx.x;

    // ---- setup: neighbor indices + positional MLP stage 1 (folded bn_p) ----
    if (tid < KN) {
        int k = tid;
        int nb = nei[n * KN + k];
        nb_s[k] = nb;
        float px = xyz[n * 3], py = xyz[n * 3 + 1], pz = xyz[n * 3 + 2];
        float d0 = xyz[nb * 3] - px;
        float d1 = xyz[nb * 3 + 1] - py;
        float d2 = xyz[nb * 3 + 2] - pz;
#pragma unroll
        for (int o = 0; o < 3; o++) {
            float v = d0 * g_Wp1f[o] + d1 * g_Wp1f[3 + o] + d2 * g_Wp1f[6 + o] + g_bp1f[o];
            t_s[k][o] = fmaxf(v, 0.0f);
        }
    }
    __syncthreads();

    // ---- phase A: gather kf/vf, compute p, wv = relu(bn_w(kf-q+p)), vfp = vf+p ----
    {
        const int c = tid & 127;
        const int khalf = tid >> 7;  // 0 or 1
        const float qc = g_q[n * CH + c];
        const float swc = g_sw[c], shwc = g_shw[c];
        const float wp0 = Wp2[c], wp1v = Wp2[CH + c], wp2v = Wp2[2 * CH + c];
        const float bpc = bp2[c];
#pragma unroll
        for (int it = 0; it < 8; it++) {
            int k = it * 2 + khalf;
            int nb = nb_s[k];
            float kf = g_k[nb * CH + c];
            float vf = g_v[nb * CH + c];
            float pv = t_s[k][0] * wp0 + t_s[k][1] * wp1v + t_s[k][2] * wp2v + bpc;
            float w = (kf - qc + pv) * swc + shwc;
            wv_s[k][c] = fmaxf(w, 0.0f);
            vfp_s[k][c] = vf + pv;
        }
    }
    __syncthreads();

    // ---- phase B: h[k][j] = relu( wv[k,:] . W1T[j,:] + b1f[j] )  (FFMA2) ----
    {
        const int kk = tid >> 4;  // 0..15
        const int j = tid & 15;   // 0..15
        const float* wrow = wv_s[kk];
        const float* w1row = &g_W1T[j * CH];
        unsigned long long acc0 = 0ULL, acc1 = 0ULL;
#pragma unroll
        for (int c4 = 0; c4 < CH; c4 += 4) {
            ulonglong2 wvp = *(const ulonglong2*)&wrow[c4];
            ulonglong2 w1p = *(const ulonglong2*)&w1row[c4];
            ffma2(acc0, wvp.x, w1p.x);
            ffma2(acc1, wvp.y, w1p.y);
        }
        float h = lo32(acc0) + hi32(acc0) + lo32(acc1) + hi32(acc1) + g_b1f[j];
        h2_s[kk][j] = fmaxf(h, 0.0f);
    }
    __syncthreads();

    // ---- logits: lg[k][j2] = h2[k,:] . Ww2[:,j2] + bw2[j2] ----
    {
        const int kk = tid >> 4;
        const int j2 = tid & 15;
        float acc = bw2[j2];
#pragma unroll
        for (int j = 0; j < CS; j++)
            acc += h2_s[kk][j] * Ww2[j * CS + j2];
        lg_s[kk][j2] = acc;
    }
    __syncthreads();

    // ---- softmax over K per channel-group j ----
    if (tid < CS) {
        const int j = tid;
        float m = -1e30f;
#pragma unroll
        for (int k = 0; k < KN; k++) m = fmaxf(m, lg_s[k][j]);
        float e[KN];
        float s = 0.0f;
#pragma unroll
        for (int k = 0; k < KN; k++) {
            e[k] = __expf(lg_s[k][j] - m);
            s += e[k];
        }
        float inv = 1.0f / s;
#pragma unroll
        for (int k = 0; k < KN; k++) wgt_s[k][j] = e[k] * inv;
    }
    __syncthreads();

    // ---- phase D: grouped aggregation + residual + leaky_relu ----
    if (tid < CH) {
        const int c = tid;
        const int j = c & 15;
        float acc = 0.0f;
#pragma unroll
        for (int k = 0; k < KN; k++)
            acc += vfp_s[k][c] * wgt_s[k][j];
        float v = acc + feats[n * CH + c];
        out[n * CH + c] = (v > 0.0f) ? v : 0.1f * v;
    }
}

// ---------------- launch ------------------------------------------------------------
extern "C" void kernel_launch(void* const* d_in, const int* in_sizes, int n_in,
                              void* d_out, int out_size) {
    const float* xyz   = (const float*)d_in[0];
    const float* feats = (const float*)d_in[1];
    const int*   nei   = (const int*)d_in[2];
    const float* Wq = (const float*)d_in[3];
    const float* bq = (const float*)d_in[4];
    const float* Wk = (const float*)d_in[5];
    const float* bk = (const float*)d_in[6];
    const float* Wv = (const float*)d_in[7];
    const float* bv = (const float*)d_in[8];
    const float* Wp1 = (const float*)d_in[9];
    const float* bp1 = (const float*)d_in[10];
    const float* p_gamma = (const float*)d_in[11];
    const float* p_beta  = (const float*)d_in[12];
    const float* p_mean  = (const float*)d_in[13];
    const float* p_var   = (const float*)d_in[14];
    const float* Wp2 = (const float*)d_in[15];
    const float* bp2 = (const float*)d_in[16];
    const float* w_gamma = (const float*)d_in[17];
    const float* w_beta  = (const float*)d_in[18];
    const float* w_mean  = (const float*)d_in[19];
    const float* w_var   = (const float*)d_in[20];
    const float* Ww1 = (const float*)d_in[21];
    const float* bw1 = (const float*)d_in[22];
    const float* w1_gamma = (const float*)d_in[23];
    const float* w1_beta  = (const float*)d_in[24];
    const float* w1_mean  = (const float*)d_in[25];
    const float* w1_var   = (const float*)d_in[26];
    const float* Ww2 = (const float*)d_in[27];
    const float* bw2 = (const float*)d_in[28];
    float* out = (float*)d_out;

    prep_kernel<<<1, 256>>>(w_gamma, w_beta, w_mean, w_var, Ww1, bw1, w1_gamma,
                            w1_beta, w1_mean, w1_var, Wp1, bp1, p_gamma, p_beta,
                            p_mean, p_var);
    qkv_gemm<<<dim3(625, 3), 256>>>(feats, Wq, bq, Wk, bk, Wv, bv);
    pt_main<<<NPTS, 256>>>(xyz, feats, nei, Wp2, bp2, Ww2, bw2, out);
}

// round 3
// speedup vs baseline: 2.6851x; 2.6851x over previous
#include <cuda_runtime.h>

#define NPTS 40000
#define KN 16
#define CH 128
#define CS 16          // C / S
#define CHP 132        // padded row stride (132*4 = 528 B = 33*16, kills smem bank conflicts)
#define EPSBN 1e-5f

// ---------------- scratch (no allocation allowed -> __device__ globals) -------------
__device__ float g_q[NPTS * CH];
__device__ float g_k[NPTS * CH];
__device__ float g_v[NPTS * CH];
__device__ float g_W1T[CS * CH];   // folded (Ww1 * s1)^T, row j contiguous over c
__device__ float g_sw[CH];         // bn_w scale
__device__ float g_shw[CH];        // bn_w shift
__device__ float g_b1f[CS];        // folded bw1 through bn1
__device__ float g_Wp1f[9];        // Wp1 with bn_p scale folded into columns
__device__ float g_bp1f[3];

// packed fp32x2 FMA (FFMA2) — 2 FLOP-lanes per instruction on sm_103a
__device__ __forceinline__ void ffma2(unsigned long long& d,
                                      unsigned long long a,
                                      unsigned long long b) {
    asm("fma.rn.f32x2 %0, %1, %2, %0;" : "+l"(d) : "l"(a), "l"(b));
}

__device__ __forceinline__ unsigned long long dup2(float f) {
    unsigned int u = __float_as_uint(f);
    return ((unsigned long long)u << 32) | (unsigned long long)u;
}

__device__ __forceinline__ float lo32(unsigned long long v) {
    return __uint_as_float((unsigned int)v);
}
__device__ __forceinline__ float hi32(unsigned long long v) {
    return __uint_as_float((unsigned int)(v >> 32));
}

// ---------------- kernel 0: fold BN params into weights -----------------------------
__global__ void prep_kernel(const float* __restrict__ w_gamma, const float* __restrict__ w_beta,
                            const float* __restrict__ w_mean, const float* __restrict__ w_var,
                            const float* __restrict__ Ww1, const float* __restrict__ bw1,
                            const float* __restrict__ w1_gamma, const float* __restrict__ w1_beta,
                            const float* __restrict__ w1_mean, const float* __restrict__ w1_var,
                            const float* __restrict__ Wp1, const float* __restrict__ bp1,
                            const float* __restrict__ p_gamma, const float* __restrict__ p_beta,
                            const float* __restrict__ p_mean, const float* __restrict__ p_var) {
    int t = threadIdx.x;
    if (t < CH) {
        float s = w_gamma[t] * rsqrtf(w_var[t] + EPSBN);
        g_sw[t] = s;
        g_shw[t] = w_beta[t] - w_mean[t] * s;
    }
    for (int idx = t; idx < CS * CH; idx += blockDim.x) {
        int j = idx / CH, c = idx % CH;
        float s1 = w1_gamma[j] * rsqrtf(w1_var[j] + EPSBN);
        g_W1T[idx] = Ww1[c * CS + j] * s1;
    }
    if (t < CS) {
        float s1 = w1_gamma[t] * rsqrtf(w1_var[t] + EPSBN);
        g_b1f[t] = (bw1[t] - w1_mean[t]) * s1 + w1_beta[t];
    }
    if (t < 9) {
        int o = t % 3;
        float sp = p_gamma[o] * rsqrtf(p_var[o] + EPSBN);
        g_Wp1f[t] = Wp1[t] * sp;
    }
    if (t < 3) {
        float sp = p_gamma[t] * rsqrtf(p_var[t] + EPSBN);
        g_bp1f[t] = (bp1[t] - p_mean[t]) * sp + p_beta[t];
    }
}

// ---------------- kernel 1: fused q/k/v GEMM (FFMA2 register-tiled) -----------------
__global__ __launch_bounds__(256, 2) void qkv_gemm(
    const float* __restrict__ x,
    const float* __restrict__ Wq, const float* __restrict__ bq,
    const float* __restrict__ Wk, const float* __restrict__ bk,
    const float* __restrict__ Wv, const float* __restrict__ bv) {
    const float* W;
    const float* bias;
    float* out;
    if (blockIdx.y == 0)      { W = Wq; bias = bq; out = g_q; }
    else if (blockIdx.y == 1) { W = Wk; bias = bk; out = g_k; }
    else                      { W = Wv; bias = bv; out = g_v; }

    __shared__ __align__(16) unsigned long long A2s[16][64];  // A duplicated as f32x2
    __shared__ __align__(16) float Bs[16][128];

    const int tid = threadIdx.x;
    const int tm = tid >> 5;   // warp id 0..7 -> rows tm*8..tm*8+7
    const int tn = tid & 31;   // 0..31      -> cols tn*4..tn*4+3
    const int row0 = blockIdx.x * 64;

    unsigned long long acc[8][2];
#pragma unroll
    for (int r = 0; r < 8; r++) { acc[r][0] = 0ULL; acc[r][1] = 0ULL; }

    for (int kt = 0; kt < 8; kt++) {
        const int k0 = kt * 16;
        {
            int ar = tid >> 2;
            int ac = (tid & 3) * 4;
            float4 av = *(const float4*)&x[(row0 + ar) * CH + k0 + ac];
            A2s[ac + 0][ar] = dup2(av.x);
            A2s[ac + 1][ar] = dup2(av.y);
            A2s[ac + 2][ar] = dup2(av.z);
            A2s[ac + 3][ar] = dup2(av.w);
        }
#pragma unroll
        for (int i = 0; i < 2; i++) {
            int f4 = tid * 2 + i;
            int bkr = f4 >> 5;
            int bc = (f4 & 31) * 4;
            *(float4*)&Bs[bkr][bc] = *(const float4*)&W[(k0 + bkr) * CH + bc];
        }
        __syncthreads();
#pragma unroll
        for (int kk = 0; kk < 16; kk++) {
            unsigned long long b0 = *(const unsigned long long*)&Bs[kk][tn * 4];
            unsigned long long b1 = *(const unsigned long long*)&Bs[kk][tn * 4 + 2];
#pragma unroll
            for (int r = 0; r < 8; r++) {
                unsigned long long a = A2s[kk][tm * 8 + r];
                ffma2(acc[r][0], a, b0);
                ffma2(acc[r][1], a, b1);
            }
        }
        __syncthreads();
    }

    const float bb0 = bias[tn * 4], bb1 = bias[tn * 4 + 1];
    const float bb2 = bias[tn * 4 + 2], bb3 = bias[tn * 4 + 3];
#pragma unroll
    for (int r = 0; r < 8; r++) {
        float4 v;
        v.x = lo32(acc[r][0]) + bb0;
        v.y = hi32(acc[r][0]) + bb1;
        v.z = lo32(acc[r][1]) + bb2;
        v.w = hi32(acc[r][1]) + bb3;
        *(float4*)&out[(row0 + tm * 8 + r) * CH + tn * 4] = v;
    }
}

// ---------------- kernel 2: fused attention per point -------------------------------
__global__ __launch_bounds__(256) void pt_main(
    const float* __restrict__ xyz, const float* __restrict__ feats,
    const int* __restrict__ nei,
    const float* __restrict__ Wp2, const float* __restrict__ bp2,
    const float* __restrict__ Ww2, const float* __restrict__ bw2,
    float* __restrict__ out) {
    __shared__ __align__(16) float wv_s[KN][CHP];    // relu(bn_w(kf - q + p)), padded rows
    __shared__ __align__(16) float vfp_s[KN][CHP];   // vf + p, padded rows
    __shared__ __align__(16) float W1s[CS][CHP];     // W1T staged, padded rows
    __shared__ __align__(16) float Ww2s[CS][CS];
    __shared__ float bw2s[CS];
    __shared__ float t_s[KN][4];                     // relu'd positional 3-vector
    __shared__ int nb_s[KN];
    __shared__ float lg_s[KN][17];
    __shared__ float wgt_s[KN][17];

    const int n = blockIdx.x;
    const int tid = threadIdx.x;

    // ---- setup: neighbor indices + positional MLP stage 1 + weight staging ----
    if (tid < KN) {
        int k = tid;
        int nb = nei[n * KN + k];
        nb_s[k] = nb;
        float px = xyz[n * 3], py = xyz[n * 3 + 1], pz = xyz[n * 3 + 2];
        float d0 = xyz[nb * 3] - px;
        float d1 = xyz[nb * 3 + 1] - py;
        float d2 = xyz[nb * 3 + 2] - pz;
#pragma unroll
        for (int o = 0; o < 3; o++) {
            float v = d0 * g_Wp1f[o] + d1 * g_Wp1f[3 + o] + d2 * g_Wp1f[6 + o] + g_bp1f[o];
            t_s[k][o] = fmaxf(v, 0.0f);
        }
    }
    // stage W1T (2048 floats = 512 float4; 2 per thread) into padded smem
#pragma unroll
    for (int i = 0; i < 2; i++) {
        int f4 = tid + i * 256;
        int row = f4 >> 5;
        int c4 = (f4 & 31) * 4;
        *(float4*)&W1s[row][c4] = *(const float4*)&g_W1T[row * CH + c4];
    }
    if (tid < 64) *(float4*)&Ww2s[0][tid * 4] = *(const float4*)&Ww2[tid * 4];
    if (tid >= 64 && tid < 64 + CS) bw2s[tid - 64] = bw2[tid - 64];
    __syncthreads();

    // ---- phase A: gather kf/vf (float4), compute p, wv, vfp ----
    {
        const int c4 = (tid & 31) * 4;     // lane -> 4 channels, warp covers full row
        const int k2 = tid >> 5;           // warp id -> k and k+8
        const float4 q4  = *(const float4*)&g_q[n * CH + c4];
        const float4 sw4 = *(const float4*)&g_sw[c4];
        const float4 sh4 = *(const float4*)&g_shw[c4];
        const float4 wpa = *(const float4*)&Wp2[0 * CH + c4];
        const float4 wpb = *(const float4*)&Wp2[1 * CH + c4];
        const float4 wpc = *(const float4*)&Wp2[2 * CH + c4];
        const float4 bp4 = *(const float4*)&bp2[c4];
#pragma unroll
        for (int it = 0; it < 2; it++) {
            const int k = k2 + it * 8;
            const int nb = nb_s[k];
            const float4 kf = *(const float4*)&g_k[nb * CH + c4];
            const float4 vf = *(const float4*)&g_v[nb * CH + c4];
            const float t0 = t_s[k][0], t1 = t_s[k][1], t2 = t_s[k][2];
            float4 pv, wv, vp;
            pv.x = t0 * wpa.x + t1 * wpb.x + t2 * wpc.x + bp4.x;
            pv.y = t0 * wpa.y + t1 * wpb.y + t2 * wpc.y + bp4.y;
            pv.z = t0 * wpa.z + t1 * wpb.z + t2 * wpc.z + bp4.z;
            pv.w = t0 * wpa.w + t1 * wpb.w + t2 * wpc.w + bp4.w;
            wv.x = fmaxf((kf.x - q4.x + pv.x) * sw4.x + sh4.x, 0.0f);
            wv.y = fmaxf((kf.y - q4.y + pv.y) * sw4.y + sh4.y, 0.0f);
            wv.z = fmaxf((kf.z - q4.z + pv.z) * sw4.z + sh4.z, 0.0f);
            wv.w = fmaxf((kf.w - q4.w + pv.w) * sw4.w + sh4.w, 0.0f);
            vp.x = vf.x + pv.x;
            vp.y = vf.y + pv.y;
            vp.z = vf.z + pv.z;
            vp.w = vf.w + pv.w;
            *(float4*)&wv_s[k][c4]  = wv;
            *(float4*)&vfp_s[k][c4] = vp;
        }
    }
    __syncthreads();

    // ---- phase B: h[k][j] = relu(wv[k,:] . W1s[j,:] + b1f[j]) ; logits via shfl ----
    {
        const int kk = tid >> 4;   // 0..15 (half-warp = one k)
        const int j  = tid & 15;   // 0..15
        const float* wrow  = wv_s[kk];
        const float* w1row = W1s[j];
        unsigned long long acc0 = 0ULL, acc1 = 0ULL;
#pragma unroll
        for (int c4 = 0; c4 < CH; c4 += 4) {
            ulonglong2 a = *(const ulonglong2*)&wrow[c4];
            ulonglong2 b = *(const ulonglong2*)&w1row[c4];
            ffma2(acc0, a.x, b.x);
            ffma2(acc1, a.y, b.y);
        }
        float h = lo32(acc0) + hi32(acc0) + lo32(acc1) + hi32(acc1) + g_b1f[j];
        h = fmaxf(h, 0.0f);
        // fused logits: half-warp lanes hold h[kk][0..15]
        float lg = bw2s[j];
#pragma unroll
        for (int jj = 0; jj < CS; jj++)
            lg += __shfl_sync(0xffffffffu, h, jj, 16) * Ww2s[jj][j];
        lg_s[kk][j] = lg;
    }
    __syncthreads();

    // ---- softmax over K per channel-group j ----
    if (tid < CS) {
        const int j = tid;
        float m = -1e30f;
#pragma unroll
        for (int k = 0; k < KN; k++) m = fmaxf(m, lg_s[k][j]);
        float e[KN];
        float s = 0.0f;
#pragma unroll
        for (int k = 0; k < KN; k++) {
            e[k] = __expf(lg_s[k][j] - m);
            s += e[k];
        }
        float inv = 1.0f / s;
#pragma unroll
        for (int k = 0; k < KN; k++) wgt_s[k][j] = e[k] * inv;
    }
    __syncthreads();

    // ---- phase D: grouped aggregation + residual + leaky_relu ----
    if (tid < CH) {
        const int c = tid;
        const int j = c & 15;
        float acc = 0.0f;
#pragma unroll
        for (int k = 0; k < KN; k++)
            acc += vfp_s[k][c] * wgt_s[k][j];
        float v = acc + feats[n * CH + c];
        out[n * CH + c] = (v > 0.0f) ? v : 0.1f * v;
    }
}

// ---------------- launch ------------------------------------------------------------
extern "C" void kernel_launch(void* const* d_in, const int* in_sizes, int n_in,
                              void* d_out, int out_size) {
    const float* xyz   = (const float*)d_in[0];
    const float* feats = (const float*)d_in[1];
    const int*   nei   = (const int*)d_in[2];
    const float* Wq = (const float*)d_in[3];
    const float* bq = (const float*)d_in[4];
    const float* Wk = (const float*)d_in[5];
    const float* bk = (const float*)d_in[6];
    const float* Wv = (const float*)d_in[7];
    const float* bv = (const float*)d_in[8];
    const float* Wp1 = (const float*)d_in[9];
    const float* bp1 = (const float*)d_in[10];
    const float* p_gamma = (const float*)d_in[11];
    const float* p_beta  = (const float*)d_in[12];
    const float* p_mean  = (const float*)d_in[13];
    const float* p_var   = (const float*)d_in[14];
    const float* Wp2 = (const float*)d_in[15];
    const float* bp2 = (const float*)d_in[16];
    const float* w_gamma = (const float*)d_in[17];
    const float* w_beta  = (const float*)d_in[18];
    const float* w_mean  = (const float*)d_in[19];
    const float* w_var   = (const float*)d_in[20];
    const float* Ww1 = (const float*)d_in[21];
    const float* bw1 = (const float*)d_in[22];
    const float* w1_gamma = (const float*)d_in[23];
    const float* w1_beta  = (const float*)d_in[24];
    const float* w1_mean  = (const float*)d_in[25];
    const float* w1_var   = (const float*)d_in[26];
    const float* Ww2 = (const float*)d_in[27];
    const float* bw2 = (const float*)d_in[28];
    float* out = (float*)d_out;

    prep_kernel<<<1, 256>>>(w_gamma, w_beta, w_mean, w_var, Ww1, bw1, w1_gamma,
                            w1_beta, w1_mean, w1_var, Wp1, bp1, p_gamma, p_beta,
                            p_mean, p_var);
    qkv_gemm<<<dim3(625, 3), 256>>>(feats, Wq, bq, Wk, bk, Wv, bv);
    pt_main<<<NPTS, 256>>>(xyz, feats, nei, Wp2, bp2, Ww2, bw2, out);
}

// round 5
// speedup vs baseline: 3.0938x; 1.1522x over previous
#include <cuda_runtime.h>

#define NPTS 40000
#define KN 16
#define CH 128
#define CS 16          // C / S
#define CHP 132        // padded row stride (528 B = 33*16) for wv/vfp rows
#define EPSBN 1e-5f

// ---------------- scratch (no allocation allowed -> __device__ globals) -------------
__device__ float g_q[NPTS * CH];
__device__ float g_k[NPTS * CH];
__device__ float g_v[NPTS * CH];
// W1 re-layout for register-resident phase B:
// g_W1R[((w*16 + j)*16) + ci] = bn1-folded W1T[j][16*w + ci],  w,j in 0..15/0..15? w in 0..7
__device__ float g_W1R[CS * CH];
__device__ float g_sw[CH];         // bn_w scale
__device__ float g_shw[CH];        // bn_w shift
__device__ float g_b1f[CS];        // folded bw1 through bn1
__device__ float g_Wp1f[9];        // Wp1 with bn_p scale folded
__device__ float g_bp1f[3];

// packed fp32x2 FMA (FFMA2) — 2 FLOP-lanes per instruction on sm_103a
__device__ __forceinline__ void ffma2(unsigned long long& d,
                                      unsigned long long a,
                                      unsigned long long b) {
    asm("fma.rn.f32x2 %0, %1, %2, %0;" : "+l"(d) : "l"(a), "l"(b));
}

__device__ __forceinline__ unsigned long long dup2(float f) {
    unsigned int u = __float_as_uint(f);
    return ((unsigned long long)u << 32) | (unsigned long long)u;
}

__device__ __forceinline__ float lo32(unsigned long long v) {
    return __uint_as_float((unsigned int)v);
}
__device__ __forceinline__ float hi32(unsigned long long v) {
    return __uint_as_float((unsigned int)(v >> 32));
}

// ---------------- kernel 0: fold BN params into weights -----------------------------
__global__ void prep_kernel(const float* __restrict__ w_gamma, const float* __restrict__ w_beta,
                            const float* __restrict__ w_mean, const float* __restrict__ w_var,
                            const float* __restrict__ Ww1, const float* __restrict__ bw1,
                            const float* __restrict__ w1_gamma, const float* __restrict__ w1_beta,
                            const float* __restrict__ w1_mean, const float* __restrict__ w1_var,
                            const float* __restrict__ Wp1, const float* __restrict__ bp1,
                            const float* __restrict__ p_gamma, const float* __restrict__ p_beta,
                            const float* __restrict__ p_mean, const float* __restrict__ p_var) {
    int t = threadIdx.x;
    if (t < CH) {
        float s = w_gamma[t] * rsqrtf(w_var[t] + EPSBN);
        g_sw[t] = s;
        g_shw[t] = w_beta[t] - w_mean[t] * s;
    }
    // W1 register re-layout: idx = (w*16 + j)*16 + ci ; channel c = 16*w + ci
    for (int idx = t; idx < CS * CH; idx += blockDim.x) {
        int ci = idx & 15;
        int j = (idx >> 4) & 15;
        int w = idx >> 8;
        int c = w * 16 + ci;
        float s1 = w1_gamma[j] * rsqrtf(w1_var[j] + EPSBN);
        g_W1R[idx] = Ww1[c * CS + j] * s1;
    }
    if (t < CS) {
        float s1 = w1_gamma[t] * rsqrtf(w1_var[t] + EPSBN);
        g_b1f[t] = (bw1[t] - w1_mean[t]) * s1 + w1_beta[t];
    }
    if (t < 9) {
        int o = t % 3;
        float sp = p_gamma[o] * rsqrtf(p_var[o] + EPSBN);
        g_Wp1f[t] = Wp1[t] * sp;
    }
    if (t < 3) {
        float sp = p_gamma[t] * rsqrtf(p_var[t] + EPSBN);
        g_bp1f[t] = (bp1[t] - p_mean[t]) * sp + p_beta[t];
    }
}

// ---------------- kernel 1: fused q/k/v GEMM (FFMA2 register-tiled) -----------------
__global__ __launch_bounds__(256, 2) void qkv_gemm(
    const float* __restrict__ x,
    const float* __restrict__ Wq, const float* __restrict__ bq,
    const float* __restrict__ Wk, const float* __restrict__ bk,
    const float* __restrict__ Wv, const float* __restrict__ bv) {
    const float* W;
    const float* bias;
    float* out;
    if (blockIdx.y == 0)      { W = Wq; bias = bq; out = g_q; }
    else if (blockIdx.y == 1) { W = Wk; bias = bk; out = g_k; }
    else                      { W = Wv; bias = bv; out = g_v; }

    __shared__ __align__(16) unsigned long long A2s[16][64];
    __shared__ __align__(16) float Bs[16][128];

    const int tid = threadIdx.x;
    const int tm = tid >> 5;
    const int tn = tid & 31;
    const int row0 = blockIdx.x * 64;

    unsigned long long acc[8][2];
#pragma unroll
    for (int r = 0; r < 8; r++) { acc[r][0] = 0ULL; acc[r][1] = 0ULL; }

    for (int kt = 0; kt < 8; kt++) {
        const int k0 = kt * 16;
        {
            int ar = tid >> 2;
            int ac = (tid & 3) * 4;
            float4 av = *(const float4*)&x[(row0 + ar) * CH + k0 + ac];
            A2s[ac + 0][ar] = dup2(av.x);
            A2s[ac + 1][ar] = dup2(av.y);
            A2s[ac + 2][ar] = dup2(av.z);
            A2s[ac + 3][ar] = dup2(av.w);
        }
#pragma unroll
        for (int i = 0; i < 2; i++) {
            int f4 = tid * 2 + i;
            int bkr = f4 >> 5;
            int bc = (f4 & 31) * 4;
            *(float4*)&Bs[bkr][bc] = *(const float4*)&W[(k0 + bkr) * CH + bc];
        }
        __syncthreads();
#pragma unroll
        for (int kk = 0; kk < 16; kk++) {
            unsigned long long b0 = *(const unsigned long long*)&Bs[kk][tn * 4];
            unsigned long long b1 = *(const unsigned long long*)&Bs[kk][tn * 4 + 2];
#pragma unroll
            for (int r = 0; r < 8; r++) {
                unsigned long long a = A2s[kk][tm * 8 + r];
                ffma2(acc[r][0], a, b0);
                ffma2(acc[r][1], a, b1);
            }
        }
        __syncthreads();
    }

    const float bb0 = bias[tn * 4], bb1 = bias[tn * 4 + 1];
    const float bb2 = bias[tn * 4 + 2], bb3 = bias[tn * 4 + 3];
#pragma unroll
    for (int r = 0; r < 8; r++) {
        float4 v;
        v.x = lo32(acc[r][0]) + bb0;
        v.y = hi32(acc[r][0]) + bb1;
        v.z = lo32(acc[r][1]) + bb2;
        v.w = hi32(acc[r][1]) + bb3;
        *(float4*)&out[(row0 + tm * 8 + r) * CH + tn * 4] = v;
    }
}

// ---------------- kernel 2: fused attention per point -------------------------------
__global__ __launch_bounds__(256) void pt_main(
    const float* __restrict__ xyz, const float* __restrict__ feats,
    const int* __restrict__ nei,
    const float* __restrict__ Wp2, const float* __restrict__ bp2,
    const float* __restrict__ Ww2, const float* __restrict__ bw2,
    float* __restrict__ out) {
    __shared__ __align__(16) float wv_s[KN][CHP];    // relu(bn_w(kf - q + p))
    __shared__ __align__(16) float vfp_s[KN][CHP];   // vf + p
    __shared__ __align__(16) float part_s[8][KN][CS]; // split-K partials [w][k][j]
    __shared__ __align__(16) float Ww2s[CS][CS];
    __shared__ float bw2s[CS];
    __shared__ float t_s[KN][4];
    __shared__ int nb_s[KN];
    __shared__ float lg_s[KN][CS];
    __shared__ float wgt_s[KN][CS];

    const int n = blockIdx.x;
    const int tid = threadIdx.x;

    // ---- setup: neighbor indices + positional MLP stage 1 + tiny weight staging ----
    if (tid < KN) {
        int k = tid;
        int nb = nei[n * KN + k];
        nb_s[k] = nb;
        float px = xyz[n * 3], py = xyz[n * 3 + 1], pz = xyz[n * 3 + 2];
        float d0 = xyz[nb * 3] - px;
        float d1 = xyz[nb * 3 + 1] - py;
        float d2 = xyz[nb * 3 + 2] - pz;
#pragma unroll
        for (int o = 0; o < 3; o++) {
            float v = d0 * g_Wp1f[o] + d1 * g_Wp1f[3 + o] + d2 * g_Wp1f[6 + o] + g_bp1f[o];
            t_s[k][o] = fmaxf(v, 0.0f);
        }
    }
    if (tid >= 64 && tid < 128) *(float4*)&Ww2s[0][(tid - 64) * 4] = *(const float4*)&Ww2[(tid - 64) * 4];
    if (tid >= 128 && tid < 128 + CS) bw2s[tid - 128] = bw2[tid - 128];

    // W1 register slice (independent of smem; load before sync to overlap latency):
    // warp w owns channels [16w,16w+16); lane (kh,j) holds W1T[j][16w..16w+15]
    const int wrp = tid >> 5;
    const int lane = tid & 31;
    const int j = lane & 15;
    const int kh = lane >> 4;
    const int c0 = wrp * 16;
    ulonglong2 w1a, w1b, w1c, w1d;
    {
        const ulonglong2* w1p = (const ulonglong2*)&g_W1R[(wrp * 16 + j) * 16];
        w1a = w1p[0]; w1b = w1p[1]; w1c = w1p[2]; w1d = w1p[3];
    }
    __syncthreads();

    // ---- phase A: gather kf/vf (float4), compute p, wv, vfp ----
    {
        const int c4 = (tid & 31) * 4;
        const int k2 = tid >> 5;
        const float4 q4  = *(const float4*)&g_q[n * CH + c4];
        const float4 sw4 = *(const float4*)&g_sw[c4];
        const float4 sh4 = *(const float4*)&g_shw[c4];
        const float4 wpa = *(const float4*)&Wp2[0 * CH + c4];
        const float4 wpb = *(const float4*)&Wp2[1 * CH + c4];
        const float4 wpc = *(const float4*)&Wp2[2 * CH + c4];
        const float4 bp4 = *(const float4*)&bp2[c4];
#pragma unroll
        for (int it = 0; it < 2; it++) {
            const int k = k2 + it * 8;
            const int nb = nb_s[k];
            const float4 kf = *(const float4*)&g_k[nb * CH + c4];
            const float4 vf = *(const float4*)&g_v[nb * CH + c4];
            const float t0 = t_s[k][0], t1 = t_s[k][1], t2 = t_s[k][2];
            float4 pv, wv, vp;
            pv.x = t0 * wpa.x + t1 * wpb.x + t2 * wpc.x + bp4.x;
            pv.y = t0 * wpa.y + t1 * wpb.y + t2 * wpc.y + bp4.y;
            pv.z = t0 * wpa.z + t1 * wpb.z + t2 * wpc.z + bp4.z;
            pv.w = t0 * wpa.w + t1 * wpb.w + t2 * wpc.w + bp4.w;
            wv.x = fmaxf((kf.x - q4.x + pv.x) * sw4.x + sh4.x, 0.0f);
            wv.y = fmaxf((kf.y - q4.y + pv.y) * sw4.y + sh4.y, 0.0f);
            wv.z = fmaxf((kf.z - q4.z + pv.z) * sw4.z + sh4.z, 0.0f);
            wv.w = fmaxf((kf.w - q4.w + pv.w) * sw4.w + sh4.w, 0.0f);
            vp.x = vf.x + pv.x;
            vp.y = vf.y + pv.y;
            vp.z = vf.z + pv.z;
            vp.w = vf.w + pv.w;
            *(float4*)&wv_s[k][c4]  = wv;
            *(float4*)&vfp_s[k][c4] = vp;
        }
    }
    __syncthreads();

    // ---- phase B: split-K partials. Warp w: channels [16w,16w+16), lane (kh,j).
    //      wv rows read ONCE via 16-lane broadcast; W1 in registers. ----
    {
#pragma unroll
        for (int i = 0; i < 8; i++) {
            const int k = i * 2 + kh;
            const ulonglong2* vp = (const ulonglong2*)&wv_s[k][c0];
            ulonglong2 va = vp[0], vb = vp[1], vc = vp[2], vd = vp[3];
            unsigned long long acc = 0ULL;
            ffma2(acc, va.x, w1a.x);
            ffma2(acc, va.y, w1a.y);
            ffma2(acc, vb.x, w1b.x);
            ffma2(acc, vb.y, w1b.y);
            ffma2(acc, vc.x, w1c.x);
            ffma2(acc, vc.y, w1c.y);
            ffma2(acc, vd.x, w1d.x);
            ffma2(acc, vd.y, w1d.y);
            part_s[wrp][k][j] = lo32(acc) + hi32(acc);
        }
    }
    __syncthreads();

    // ---- reduction + relu + fused logits via width-16 shfl ----
    {
        const int kk = tid >> 4;   // 0..15
        const int jj = tid & 15;   // 0..15
        float h = g_b1f[jj];
#pragma unroll
        for (int w = 0; w < 8; w++) h += part_s[w][kk][jj];
        h = fmaxf(h, 0.0f);
        float lg = bw2s[jj];
#pragma unroll
        for (int j2 = 0; j2 < CS; j2++)
            lg += __shfl_sync(0xffffffffu, h, j2, 16) * Ww2s[j2][jj];
        lg_s[kk][jj] = lg;
    }
    __syncthreads();

    // ---- softmax over K per channel-group j ----
    if (tid < CS) {
        const int jj = tid;
        float m = -1e30f;
#pragma unroll
        for (int k = 0; k < KN; k++) m = fmaxf(m, lg_s[k][jj]);
        float e[KN];
        float s = 0.0f;
#pragma unroll
        for (int k = 0; k < KN; k++) {
            e[k] = __expf(lg_s[k][jj] - m);
            s += e[k];
        }
        float inv = 1.0f / s;
#pragma unroll
        for (int k = 0; k < KN; k++) wgt_s[k][jj] = e[k] * inv;
    }
    __syncthreads();

    // ---- phase D: grouped aggregation + residual + leaky_relu ----
    if (tid < CH) {
        const int c = tid;
        const int jj = c & 15;
        float acc = 0.0f;
#pragma unroll
        for (int k = 0; k < KN; k++)
            acc += vfp_s[k][c] * wgt_s[k][jj];
        float v = acc + feats[n * CH + c];
        out[n * CH + c] = (v > 0.0f) ? v : 0.1f * v;
    }
}

// ---------------- launch ------------------------------------------------------------
extern "C" void kernel_launch(void* const* d_in, const int* in_sizes, int n_in,
                              void* d_out, int out_size) {
    const float* xyz   = (const float*)d_in[0];
    const float* feats = (const float*)d_in[1];
    const int*   nei   = (const int*)d_in[2];
    const float* Wq = (const float*)d_in[3];
    const float* bq = (const float*)d_in[4];
    const float* Wk = (const float*)d_in[5];
    const float* bk = (const float*)d_in[6];
    const float* Wv = (const float*)d_in[7];
    const float* bv = (const float*)d_in[8];
    const float* Wp1 = (const float*)d_in[9];
    const float* bp1 = (const float*)d_in[10];
    const float* p_gamma = (const float*)d_in[11];
    const float* p_beta  = (const float*)d_in[12];
    const float* p_mean  = (const float*)d_in[13];
    const float* p_var   = (const float*)d_in[14];
    const float* Wp2 = (const float*)d_in[15];
    const float* bp2 = (const float*)d_in[16];
    const float* w_gamma = (const float*)d_in[17];
    const float* w_beta  = (const float*)d_in[18];
    const float* w_mean  = (const float*)d_in[19];
    const float* w_var   = (const float*)d_in[20];
    const float* Ww1 = (const float*)d_in[21];
    const float* bw1 = (const float*)d_in[22];
    const float* w1_gamma = (const float*)d_in[23];
    const float* w1_beta  = (const float*)d_in[24];
    const float* w1_mean  = (const float*)d_in[25];
    const float* w1_var   = (const float*)d_in[26];
    const float* Ww2 = (const float*)d_in[27];
    const float* bw2 = (const float*)d_in[28];
    float* out = (float*)d_out;

    prep_kernel<<<1, 256>>>(w_gamma, w_beta, w_mean, w_var, Ww1, bw1, w1_gamma,
                            w1_beta, w1_mean, w1_var, Wp1, bp1, p_gamma, p_beta,
                            p_mean, p_var);
    qkv_gemm<<<dim3(625, 3), 256>>>(feats, Wq, bq, Wk, bk, Wv, bv);
    pt_main<<<NPTS, 256>>>(xyz, feats, nei, Wp2, bp2, Ww2, bw2, out);
}

// round 7
// speedup vs baseline: 3.3909x; 1.0960x over previous
#include <cuda_runtime.h>

#define NPTS 40000
#define KN 16
#define CH 128
#define CS 16          // C / S
#define CHP 132        // padded row stride (528 B) — 2-way-max smem banking
#define GRIDX 592      // 4 blocks/SM * 148 SMs, persistent
#define EPSBN 1e-5f

// ---------------- scratch (no allocation allowed -> __device__ globals) -------------
__device__ float g_q[NPTS * CH];
__device__ float g_k[NPTS * CH];
__device__ float g_v[NPTS * CH];
__device__ float g_W1T[CS * CH];   // folded (Ww1 * s1)^T, row j contiguous over c
__device__ float g_sw[CH];         // bn_w scale
__device__ float g_shw[CH];        // bn_w shift
__device__ float g_b1f[CS];        // folded bw1 through bn1
__device__ float g_Wp1f[9];        // Wp1 with bn_p scale folded
__device__ float g_bp1f[3];

// packed fp32x2 FMA (FFMA2) — 2 FLOP-lanes per instruction on sm_103a
__device__ __forceinline__ void ffma2(unsigned long long& d,
                                      unsigned long long a,
                                      unsigned long long b) {
    asm("fma.rn.f32x2 %0, %1, %2, %0;" : "+l"(d) : "l"(a), "l"(b));
}

__device__ __forceinline__ unsigned long long dup2(float f) {
    unsigned int u = __float_as_uint(f);
    return ((unsigned long long)u << 32) | (unsigned long long)u;
}

__device__ __forceinline__ float lo32(unsigned long long v) {
    return __uint_as_float((unsigned int)v);
}
__device__ __forceinline__ float hi32(unsigned long long v) {
    return __uint_as_float((unsigned int)(v >> 32));
}

// ---------------- kernel 0: fold BN params into weights -----------------------------
__global__ void prep_kernel(const float* __restrict__ w_gamma, const float* __restrict__ w_beta,
                            const float* __restrict__ w_mean, const float* __restrict__ w_var,
                            const float* __restrict__ Ww1, const float* __restrict__ bw1,
                            const float* __restrict__ w1_gamma, const float* __restrict__ w1_beta,
                            const float* __restrict__ w1_mean, const float* __restrict__ w1_var,
                            const float* __restrict__ Wp1, const float* __restrict__ bp1,
                            const float* __restrict__ p_gamma, const float* __restrict__ p_beta,
                            const float* __restrict__ p_mean, const float* __restrict__ p_var) {
    int t = threadIdx.x;
    if (t < CH) {
        float s = w_gamma[t] * rsqrtf(w_var[t] + EPSBN);
        g_sw[t] = s;
        g_shw[t] = w_beta[t] - w_mean[t] * s;
    }
    for (int idx = t; idx < CS * CH; idx += blockDim.x) {
        int j = idx / CH, c = idx % CH;
        float s1 = w1_gamma[j] * rsqrtf(w1_var[j] + EPSBN);
        g_W1T[idx] = Ww1[c * CS + j] * s1;
    }
    if (t < CS) {
        float s1 = w1_gamma[t] * rsqrtf(w1_var[t] + EPSBN);
        g_b1f[t] = (bw1[t] - w1_mean[t]) * s1 + w1_beta[t];
    }
    if (t < 9) {
        int o = t % 3;
        float sp = p_gamma[o] * rsqrtf(p_var[o] + EPSBN);
        g_Wp1f[t] = Wp1[t] * sp;
    }
    if (t < 3) {
        float sp = p_gamma[t] * rsqrtf(p_var[t] + EPSBN);
        g_bp1f[t] = (bp1[t] - p_mean[t]) * sp + p_beta[t];
    }
}

// ---------------- kernel 1: fused q/k/v GEMM (FFMA2 register-tiled) -----------------
__global__ __launch_bounds__(256, 2) void qkv_gemm(
    const float* __restrict__ x,
    const float* __restrict__ Wq, const float* __restrict__ bq,
    const float* __restrict__ Wk, const float* __restrict__ bk,
    const float* __restrict__ Wv, const float* __restrict__ bv) {
    const float* W;
    const float* bias;
    float* out;
    if (blockIdx.y == 0)      { W = Wq; bias = bq; out = g_q; }
    else if (blockIdx.y == 1) { W = Wk; bias = bk; out = g_k; }
    else                      { W = Wv; bias = bv; out = g_v; }

    __shared__ __align__(16) unsigned long long A2s[16][64];
    __shared__ __align__(16) float Bs[16][128];

    const int tid = threadIdx.x;
    const int tm = tid >> 5;
    const int tn = tid & 31;
    const int row0 = blockIdx.x * 64;

    unsigned long long acc[8][2];
#pragma unroll
    for (int r = 0; r < 8; r++) { acc[r][0] = 0ULL; acc[r][1] = 0ULL; }

    for (int kt = 0; kt < 8; kt++) {
        const int k0 = kt * 16;
        {
            int ar = tid >> 2;
            int ac = (tid & 3) * 4;
            float4 av = *(const float4*)&x[(row0 + ar) * CH + k0 + ac];
            A2s[ac + 0][ar] = dup2(av.x);
            A2s[ac + 1][ar] = dup2(av.y);
            A2s[ac + 2][ar] = dup2(av.z);
            A2s[ac + 3][ar] = dup2(av.w);
        }
#pragma unroll
        for (int i = 0; i < 2; i++) {
            int f4 = tid * 2 + i;
            int bkr = f4 >> 5;
            int bc = (f4 & 31) * 4;
            *(float4*)&Bs[bkr][bc] = *(const float4*)&W[(k0 + bkr) * CH + bc];
        }
        __syncthreads();
#pragma unroll
        for (int kk = 0; kk < 16; kk++) {
            unsigned long long b0 = *(const unsigned long long*)&Bs[kk][tn * 4];
            unsigned long long b1 = *(const unsigned long long*)&Bs[kk][tn * 4 + 2];
#pragma unroll
            for (int r = 0; r < 8; r++) {
                unsigned long long a = A2s[kk][tm * 8 + r];
                ffma2(acc[r][0], a, b0);
                ffma2(acc[r][1], a, b1);
            }
        }
        __syncthreads();
    }

    const float bb0 = bias[tn * 4], bb1 = bias[tn * 4 + 1];
    const float bb2 = bias[tn * 4 + 2], bb3 = bias[tn * 4 + 3];
#pragma unroll
    for (int r = 0; r < 8; r++) {
        float4 v;
        v.x = lo32(acc[r][0]) + bb0;
        v.y = hi32(acc[r][0]) + bb1;
        v.z = lo32(acc[r][1]) + bb2;
        v.w = hi32(acc[r][1]) + bb3;
        *(float4*)&out[(row0 + tm * 8 + r) * CH + tn * 4] = v;
    }
}

// ---------------- kernel 2: persistent fused attention ------------------------------
__global__ __launch_bounds__(256, 4) void pt_main(
    const float* __restrict__ xyz, const float* __restrict__ feats,
    const int* __restrict__ nei,
    const float* __restrict__ Wp2, const float* __restrict__ bp2,
    const float* __restrict__ Ww2, const float* __restrict__ bw2,
    float* __restrict__ out) {
    __shared__ __align__(16) float wv_s[KN][CHP];
    __shared__ __align__(16) float vfp_s[KN][CHP];
    __shared__ __align__(16) float part_s[8][KN][CS];
    __shared__ __align__(16) float W1s[CS][CHP];
    __shared__ __align__(16) float Ww2s[CS][CS];
    __shared__ float bw2s[CS];
    __shared__ int   nb_s[2][KN];
    __shared__ float t_s[2][KN][4];
    __shared__ float lg_s[KN][CS];
    __shared__ float wgt_s[KN][CS];

    const int tid = threadIdx.x;
    const int wrp = tid >> 5;
    const int lane = tid & 31;
    const int jb = lane & 15;     // j index in phase B
    const int khb = lane >> 4;    // k-half in phase B
    const int c0 = wrp * 16;      // channel chunk owned by warp

    // ---- one-time staging (amortized over ~68 points) ----
#pragma unroll
    for (int i = 0; i < 2; i++) {
        int f4 = tid + i * 256;
        int row = f4 >> 5;
        int c4 = (f4 & 31) * 4;
        *(float4*)&W1s[row][c4] = *(const float4*)&g_W1T[row * CH + c4];
    }
    if (tid < 64) *(float4*)&Ww2s[0][tid * 4] = *(const float4*)&Ww2[tid * 4];
    else if (tid < 80) bw2s[tid - 64] = bw2[tid - 64];

    // ---- setup for first point (buf 0) ----
    int n = blockIdx.x;
    if (tid < KN) {
        int nb = nei[n * KN + tid];
        nb_s[0][tid] = nb;
        float px = xyz[n * 3], py = xyz[n * 3 + 1], pz = xyz[n * 3 + 2];
        float d0 = xyz[nb * 3] - px;
        float d1 = xyz[nb * 3 + 1] - py;
        float d2 = xyz[nb * 3 + 2] - pz;
#pragma unroll
        for (int o = 0; o < 3; o++) {
            float v = d0 * g_Wp1f[o] + d1 * g_Wp1f[3 + o] + d2 * g_Wp1f[6 + o] + g_bp1f[o];
            t_s[0][tid][o] = fmaxf(v, 0.0f);
        }
    }
    __syncthreads();

    int buf = 0;
    while (true) {
        const int n_next = n + GRIDX;
        const bool has_next = (n_next < NPTS);

        // ---- phase A: gather kf/vf, compute p, wv, vfp ----
        {
            const int c4 = lane * 4;
            const float4 q4  = *(const float4*)&g_q[n * CH + c4];
            const float4 sw4 = *(const float4*)&g_sw[c4];
            const float4 sh4 = *(const float4*)&g_shw[c4];
            const float4 wpa = *(const float4*)&Wp2[0 * CH + c4];
            const float4 wpb = *(const float4*)&Wp2[1 * CH + c4];
            const float4 wpc = *(const float4*)&Wp2[2 * CH + c4];
            const float4 bp4 = *(const float4*)&bp2[c4];
#pragma unroll
            for (int it = 0; it < 2; it++) {
                const int k = wrp + it * 8;
                const int nb = nb_s[buf][k];
                const float4 kf = *(const float4*)&g_k[nb * CH + c4];
                const float4 vf = *(const float4*)&g_v[nb * CH + c4];
                const float t0 = t_s[buf][k][0], t1 = t_s[buf][k][1], t2 = t_s[buf][k][2];
                float4 pv, wv, vp;
                pv.x = t0 * wpa.x + t1 * wpb.x + t2 * wpc.x + bp4.x;
                pv.y = t0 * wpa.y + t1 * wpb.y + t2 * wpc.y + bp4.y;
                pv.z = t0 * wpa.z + t1 * wpb.z + t2 * wpc.z + bp4.z;
                pv.w = t0 * wpa.w + t1 * wpb.w + t2 * wpc.w + bp4.w;
                wv.x = fmaxf((kf.x - q4.x + pv.x) * sw4.x + sh4.x, 0.0f);
                wv.y = fmaxf((kf.y - q4.y + pv.y) * sw4.y + sh4.y, 0.0f);
                wv.z = fmaxf((kf.z - q4.z + pv.z) * sw4.z + sh4.z, 0.0f);
                wv.w = fmaxf((kf.w - q4.w + pv.w) * sw4.w + sh4.w, 0.0f);
                vp.x = vf.x + pv.x;
                vp.y = vf.y + pv.y;
                vp.z = vf.z + pv.z;
                vp.w = vf.w + pv.w;
                *(float4*)&wv_s[k][c4]  = wv;
                *(float4*)&vfp_s[k][c4] = vp;
            }
        }
        __syncthreads();

        // ---- phase B: split-K partials (W1 from padded smem, wv via broadcast) ----
        {
            const ulonglong2* w1p = (const ulonglong2*)&W1s[jb][c0];
            const ulonglong2 w1a = w1p[0], w1b = w1p[1], w1c = w1p[2], w1d = w1p[3];
#pragma unroll
            for (int i = 0; i < 8; i++) {
                const int k = i * 2 + khb;
                const ulonglong2* vp = (const ulonglong2*)&wv_s[k][c0];
                ulonglong2 va = vp[0], vb = vp[1], vc = vp[2], vd = vp[3];
                unsigned long long acc = 0ULL;
                ffma2(acc, va.x, w1a.x);
                ffma2(acc, va.y, w1a.y);
                ffma2(acc, vb.x, w1b.x);
                ffma2(acc, vb.y, w1b.y);
                ffma2(acc, vc.x, w1c.x);
                ffma2(acc, vc.y, w1c.y);
                ffma2(acc, vd.x, w1d.x);
                ffma2(acc, vd.y, w1d.y);
                part_s[wrp][k][jb] = lo32(acc) + hi32(acc);
            }
        }
        // prefetch next point's neighbor list (hidden behind reduce phase)
        if (tid < KN && has_next) nb_s[buf ^ 1][tid] = nei[n_next * KN + tid];
        __syncthreads();

        // ---- reduction + relu + fused logits via width-16 shfl ----
        {
            const int kk = tid >> 4;
            const int jj = tid & 15;
            float h = g_b1f[jj];
#pragma unroll
            for (int w = 0; w < 8; w++) h += part_s[w][kk][jj];
            h = fmaxf(h, 0.0f);
            float lg = bw2s[jj];
#pragma unroll
            for (int j2 = 0; j2 < CS; j2++)
                lg += __shfl_sync(0xffffffffu, h, j2, 16) * Ww2s[j2][jj];
            lg_s[kk][jj] = lg;
        }
        __syncthreads();

        // ---- softmax (16 threads) || next-point positional setup (threads 32..47) ----
        if (tid < CS) {
            const int jj = tid;
            float m = -1e30f;
#pragma unroll
            for (int k = 0; k < KN; k++) m = fmaxf(m, lg_s[k][jj]);
            float e[KN];
            float s = 0.0f;
#pragma unroll
            for (int k = 0; k < KN; k++) {
                e[k] = __expf(lg_s[k][jj] - m);
                s += e[k];
            }
            float inv = 1.0f / s;
#pragma unroll
            for (int k = 0; k < KN; k++) wgt_s[k][jj] = e[k] * inv;
        } else if (tid >= 32 && tid < 32 + KN && has_next) {
            const int k = tid - 32;
            const int nb = nb_s[buf ^ 1][k];
            float px = xyz[n_next * 3], py = xyz[n_next * 3 + 1], pz = xyz[n_next * 3 + 2];
            float d0 = xyz[nb * 3] - px;
            float d1 = xyz[nb * 3 + 1] - py;
            float d2 = xyz[nb * 3 + 2] - pz;
#pragma unroll
            for (int o = 0; o < 3; o++) {
                float v = d0 * g_Wp1f[o] + d1 * g_Wp1f[3 + o] + d2 * g_Wp1f[6 + o] + g_bp1f[o];
                t_s[buf ^ 1][k][o] = fmaxf(v, 0.0f);
            }
        }
        __syncthreads();

        // ---- phase D: grouped aggregation + residual + leaky_relu ----
        if (tid < CH) {
            const int c = tid;
            const int jj = c & 15;
            float acc = 0.0f;
#pragma unroll
            for (int k = 0; k < KN; k++)
                acc += vfp_s[k][c] * wgt_s[k][jj];
            float v = acc + feats[n * CH + c];
            out[n * CH + c] = (v > 0.0f) ? v : 0.1f * v;
        }

        if (!has_next) break;
        n = n_next;
        buf ^= 1;
        __syncthreads();   // protect wv_s/vfp_s reuse by next phase A
    }
}

// ---------------- launch ------------------------------------------------------------
extern "C" void kernel_launch(void* const* d_in, const int* in_sizes, int n_in,
                              void* d_out, int out_size) {
    const float* xyz   = (const float*)d_in[0];
    const float* feats = (const float*)d_in[1];
    const int*   nei   = (const int*)d_in[2];
    const float* Wq = (const float*)d_in[3];
    const float* bq = (const float*)d_in[4];
    const float* Wk = (const float*)d_in[5];
    const float* bk = (const float*)d_in[6];
    const float* Wv = (const float*)d_in[7];
    const float* bv = (const float*)d_in[8];
    const float* Wp1 = (const float*)d_in[9];
    const float* bp1 = (const float*)d_in[10];
    const float* p_gamma = (const float*)d_in[11];
    const float* p_beta  = (const float*)d_in[12];
    const float* p_mean  = (const float*)d_in[13];
    const float* p_var   = (const float*)d_in[14];
    const float* Wp2 = (const float*)d_in[15];
    const float* bp2 = (const float*)d_in[16];
    const float* w_gamma = (const float*)d_in[17];
    const float* w_beta  = (const float*)d_in[18];
    const float* w_mean  = (const float*)d_in[19];
    const float* w_var   = (const float*)d_in[20];
    const float* Ww1 = (const float*)d_in[21];
    const float* bw1 = (const float*)d_in[22];
    const float* w1_gamma = (const float*)d_in[23];
    const float* w1_beta  = (const float*)d_in[24];
    const float* w1_mean  = (const float*)d_in[25];
    const float* w1_var   = (const float*)d_in[26];
    const float* Ww2 = (const float*)d_in[27];
    const float* bw2 = (const float*)d_in[28];
    float* out = (float*)d_out;

    prep_kernel<<<1, 256>>>(w_gamma, w_beta, w_mean, w_var, Ww1, bw1, w1_gamma,
                            w1_beta, w1_mean, w1_var, Wp1, bp1, p_gamma, p_beta,
                            p_mean, p_var);
    qkv_gemm<<<dim3(625, 3), 256>>>(feats, Wq, bq, Wk, bk, Wv, bv);
    pt_main<<<GRIDX, 256>>>(xyz, feats, nei, Wp2, bp2, Ww2, bw2, out);
}